// round 13
// baseline (speedup 1.0000x reference)
#include <cuda_runtime.h>
#include <math.h>
#include <stdint.h>

#define BATCH  16
#define NPTS   8192
#define NPOINT 2048
#define KNN    16
#define CIN    64
#define COUT   128

// ---------------- scratch (static device globals; no allocation allowed) ----
__device__ float  g_h[(size_t)BATCH * NPTS * COUT];      // conv output, 64 MB
__device__ int    g_knn[(size_t)BATCH * NPOINT * KNN];   // kNN indices
__device__ float  g_fsum[1024 * COUT];                   // stats partials
__device__ float  g_fsq [1024 * COUT];
__device__ float  g_scale[COUT];
__device__ float  g_shift[COUT];

// ------------------------------------------------------------ helpers ------
__device__ __forceinline__ uint32_t smem_u32(const void* p) {
    uint32_t a;
    asm("{ .reg .u64 t; cvta.to.shared.u64 t, %1; cvt.u32.u64 %0, t; }"
        : "=r"(a) : "l"(p));
    return a;
}
__device__ __forceinline__ uint32_t cluster_rank() {
    uint32_t r; asm("mov.u32 %0, %%cluster_ctarank;" : "=r"(r)); return r;
}
__device__ __forceinline__ uint32_t mapa_u32(uint32_t local, uint32_t peer) {
    uint32_t r;
    asm("mapa.shared::cluster.u32 %0, %1, %2;" : "=r"(r) : "r"(local), "r"(peer));
    return r;
}

// ---------------------------------------------------------------- FPS ------
// 8-CTA cluster per batch, 256 threads/CTA, 4 points/thread (registers).
// Per iteration:
//   dist update vs (wx,wy,wz) -> thread argmax (first-occurrence) ->
//   warp REDUX -> STS -> __syncthreads -> warp0 lanes0-7: REDUX over the 8
//   warp winners -> CTA winner (distbits, global idx, coords from slice SMEM)
//   -> lane j stores the 20B winner record into CTA j's slots[buf][rank] via
//   DSMEM -> barrier.cluster.arrive (release) / wait (acquire) -> every
//   thread reduces the 8 slots: max distbits, tie -> min global index
//   (== jnp.argmax first-occurrence) -> next centroid coords in registers.
// Double-buffered slots (buf = i&1): phase i+2 writes happen after
// barrier(i+1) completes, which is after every CTA finished its phase-i slot
// reads (reads precede that CTA's arrive at i+1) -> WAR-safe.
// rank0/tid0 streams centroid i BEFORE the update, matching the reference.
// Distance math identical (sub/mul/fma/fma, fminf) -> bit-identical sequence.
__global__ __launch_bounds__(256, 1) __cluster_dims__(8, 1, 1)
void fps_kernel(const float* __restrict__ xyz, float* __restrict__ out_xyz)
{
    __shared__ float sxs[1024], sys[1024], szs[1024];   // this CTA's slice
    __shared__ unsigned swv[8];
    __shared__ int      swi[8];
    __shared__ __align__(16) unsigned slots[2][8][8];   // [parity][srcCTA][u32x8]

    const int tid  = threadIdx.x;
    const int lane = tid & 31;
    const int warp = tid >> 5;
    const uint32_t rank = cluster_rank();
    const int batch = blockIdx.x >> 3;
    const int gbase = (int)rank * 1024;

    const uint32_t slotsAddr = smem_u32(&slots[0][0][0]);

    const float* base = xyz + (size_t)batch * NPTS * 3;

    float px[4], py[4], pz[4], dist[4];
#pragma unroll
    for (int k = 0; k < 4; k++) {
        int g = gbase + k * 256 + tid;
        px[k] = base[3 * g + 0];
        py[k] = base[3 * g + 1];
        pz[k] = base[3 * g + 2];
        dist[k] = 1e10f;
        sxs[k * 256 + tid] = px[k];
        sys[k * 256 + tid] = py[k];
        szs[k * 256 + tid] = pz[k];
    }
    // initial centroid = global point 0
    float wx = base[0], wy = base[1], wz = base[2];

    __syncthreads();

    float* oxyz = out_xyz + (size_t)batch * NPOINT * 3;

    for (int i = 0; i < NPOINT; i++) {
        if (rank == 0 && tid == 0) {
            oxyz[i * 3 + 0] = wx;
            oxyz[i * 3 + 1] = wy;
            oxyz[i * 3 + 2] = wz;
        }
        float nd[4];
#pragma unroll
        for (int k = 0; k < 4; k++) {
            float dx = px[k] - wx, dy = py[k] - wy, dz = pz[k] - wz;
            float d = dx * dx;
            d = fmaf(dy, dy, d);
            d = fmaf(dz, dz, d);
            nd[k] = fminf(dist[k], d);
            dist[k] = nd[k];
        }
        float m = fmaxf(fmaxf(nd[0], nd[1]), fmaxf(nd[2], nd[3]));
        int bi = 0;
#pragma unroll
        for (int k = 3; k >= 0; k--)              // descending -> smallest k wins
            if (nd[k] == m) bi = gbase + k * 256 + tid;

        // warp argmax (dist >= 0: float order == unsigned-bits order)
        unsigned vb   = __float_as_uint(m);
        unsigned wmax = __reduce_max_sync(0xffffffffu, vb);
        unsigned cand = (vb == wmax) ? (unsigned)bi : 0xffffffffu;
        unsigned widx = __reduce_min_sync(0xffffffffu, cand);
        if (lane == 0) { swv[warp] = wmax; swi[warp] = (int)widx; }
        __syncthreads();

        const int buf = i & 1;
        if (warp == 0 && lane < 8) {
            unsigned b8 = swv[lane];
            int      i8 = swi[lane];
            unsigned cb = __reduce_max_sync(0xffu, b8);
            unsigned c8 = (b8 == cb) ? (unsigned)i8 : 0xffffffffu;
            int      ci = (int)__reduce_min_sync(0xffu, c8);
            int l = ci - gbase;                    // CTA winner is local
            unsigned cxb = __float_as_uint(sxs[l]);
            unsigned cyb = __float_as_uint(sys[l]);
            unsigned czb = __float_as_uint(szs[l]);
            // lane j publishes this CTA's winner into CTA j's slots[buf][rank]
            uint32_t slotLocal = slotsAddr + (uint32_t)(buf * 8 + (int)rank) * 32u;
            uint32_t remSlot = mapa_u32(slotLocal, lane);
            asm volatile("st.shared::cluster.v4.b32 [%0], {%1,%2,%3,%4};"
                         :: "r"(remSlot), "r"(cb), "r"((unsigned)ci),
                            "r"(cxb), "r"(cyb) : "memory");
            asm volatile("st.shared::cluster.b32 [%0+16], %1;"
                         :: "r"(remSlot), "r"(czb) : "memory");
        }
        // release prior DSMEM stores; acquire peers' stores
        asm volatile("barrier.cluster.arrive.aligned;" ::: "memory");
        asm volatile("barrier.cluster.wait.aligned;"   ::: "memory");

        // every thread reduces the 8 CTA winners (LDS broadcasts)
        unsigned wb = 0; int wgi = 0; float nx = 0.f, ny = 0.f, nz = 0.f;
#pragma unroll
        for (int s = 0; s < 8; s++) {
            const unsigned* sl = &slots[buf][s][0];
            unsigned b  = sl[0];
            int      ix = (int)sl[1];
            float    x  = __uint_as_float(sl[2]);
            float    y  = __uint_as_float(sl[3]);
            float    z  = __uint_as_float(sl[4]);
            bool take = (s == 0) || (b > wb) || (b == wb && ix < wgi);
            if (take) { wb = b; wgi = ix; nx = x; ny = y; nz = z; }
        }
        wx = nx; wy = ny; wz = nz;
    }
    // last loop body ends with barrier + local reads; no remote writes after,
    // so exit is safe without an extra cluster barrier.
}

// ---------------------------------------------------------------- kNN ------
// 128 blocks x 256 threads; one query per thread; float4 candidate tile in
// SMEM. Register-resident unsorted top-K tournament (no dynamic indexing).
// Eviction = lexicographic-largest (dist, idx); strict '<' entry; final set
// equals lax.top_k's K-smallest-by-(value,index) set (order irrelevant).
#define TS 2048

__global__ __launch_bounds__(256)
void knn_kernel(const float* __restrict__ xyz,
                const float* __restrict__ new_xyz,
                int* __restrict__ knn_out)
{
    __shared__ float4 sp[TS];
    const int b = blockIdx.x >> 3;
    const int q = ((blockIdx.x & 7) << 8) + threadIdx.x;

    const float* nb = new_xyz + ((size_t)b * NPOINT + q) * 3;
    const float qx = nb[0], qy = nb[1], qz = nb[2];

    float kd[KNN]; int ki[KNN];
#pragma unroll
    for (int k = 0; k < KNN; k++) { kd[k] = 3.4e38f; ki[k] = -1; }
    float worstd = 3.4e38f;
    int   wslot  = 0;

    const float* base = xyz + (size_t)b * NPTS * 3;
    for (int t = 0; t < NPTS; t += TS) {
        __syncthreads();
        for (int p = threadIdx.x; p < TS; p += 256) {
            const float* src = base + (size_t)(t + p) * 3;
            sp[p] = make_float4(src[0], src[1], src[2], 0.0f);
        }
        __syncthreads();
#pragma unroll 4
        for (int j = 0; j < TS; j++) {
            float4 c = sp[j];
            float dx = qx - c.x, dy = qy - c.y, dz = qz - c.z;
            float d = dx * dx;
            d = fmaf(dy, dy, d);
            d = fmaf(dz, dz, d);
            if (d < worstd) {
                const int jj = t + j;
#pragma unroll
                for (int s = 0; s < KNN; s++)
                    if (s == wslot) { kd[s] = d; ki[s] = jj; }
                float wd = kd[0]; int wix = ki[0]; int ws = 0;
#pragma unroll
                for (int s = 1; s < KNN; s++) {
                    bool takes = (kd[s] > wd) || (kd[s] == wd && ki[s] > wix);
                    if (takes) { wd = kd[s]; wix = ki[s]; ws = s; }
                }
                worstd = wd; wslot = ws;
            }
        }
    }
    int* o = knn_out + ((size_t)b * NPOINT + q) * KNN;
#pragma unroll
    for (int k = 0; k < KNN; k++) o[k] = ki[k];
}

// ---------------------------------------------------------------- GEMM -----
__global__ __launch_bounds__(256)
void gemm_kernel(const float* __restrict__ feat,
                 const float* __restrict__ W,
                 const float* __restrict__ bias,
                 float* __restrict__ h)
{
    __shared__ float Wt[CIN * COUT];
    __shared__ float sf[32 * CIN];
    const int tid = threadIdx.x;

    for (int j = tid; j < CIN * COUT; j += 256) {
        int c = j >> 6, k = j & 63;
        Wt[k * COUT + c] = W[j];
    }
    const size_t row0 = (size_t)blockIdx.x * 32;
    const float* fb = feat + row0 * CIN;
    for (int j = tid; j < 32 * CIN; j += 256) sf[j] = fb[j];
    __syncthreads();

    const int cg = tid & 31;
    const int rg = tid >> 5;

    float acc[4][4];
#pragma unroll
    for (int r = 0; r < 4; r++)
#pragma unroll
        for (int c = 0; c < 4; c++) acc[r][c] = 0.0f;

#pragma unroll 8
    for (int k = 0; k < CIN; k++) {
        float4 wv = *(const float4*)&Wt[k * COUT + cg * 4];
        float f0 = sf[(rg * 4 + 0) * CIN + k];
        float f1 = sf[(rg * 4 + 1) * CIN + k];
        float f2 = sf[(rg * 4 + 2) * CIN + k];
        float f3 = sf[(rg * 4 + 3) * CIN + k];
        acc[0][0] = fmaf(f0, wv.x, acc[0][0]);
        acc[0][1] = fmaf(f0, wv.y, acc[0][1]);
        acc[0][2] = fmaf(f0, wv.z, acc[0][2]);
        acc[0][3] = fmaf(f0, wv.w, acc[0][3]);
        acc[1][0] = fmaf(f1, wv.x, acc[1][0]);
        acc[1][1] = fmaf(f1, wv.y, acc[1][1]);
        acc[1][2] = fmaf(f1, wv.z, acc[1][2]);
        acc[1][3] = fmaf(f1, wv.w, acc[1][3]);
        acc[2][0] = fmaf(f2, wv.x, acc[2][0]);
        acc[2][1] = fmaf(f2, wv.y, acc[2][1]);
        acc[2][2] = fmaf(f2, wv.z, acc[2][2]);
        acc[2][3] = fmaf(f2, wv.w, acc[2][3]);
        acc[3][0] = fmaf(f3, wv.x, acc[3][0]);
        acc[3][1] = fmaf(f3, wv.y, acc[3][1]);
        acc[3][2] = fmaf(f3, wv.z, acc[3][2]);
        acc[3][3] = fmaf(f3, wv.w, acc[3][3]);
    }
    const float4 bb = *(const float4*)&bias[cg * 4];
#pragma unroll
    for (int r = 0; r < 4; r++) {
        float4 o;
        o.x = acc[r][0] + bb.x;
        o.y = acc[r][1] + bb.y;
        o.z = acc[r][2] + bb.z;
        o.w = acc[r][3] + bb.w;
        *(float4*)&h[(row0 + rg * 4 + r) * COUT + cg * 4] = o;
    }
}

// ----------------------------------------------------------- BN stats ------
__global__ __launch_bounds__(256)
void stats_kernel(const float* __restrict__ h)
{
    __shared__ float4 reds[8][32];
    __shared__ float4 redq[8][32];
    const int tid = threadIdx.x;
    const int cg  = tid & 31;
    const int r   = tid >> 5;

    const float* p = h + ((size_t)blockIdx.x * 128 + r) * COUT + cg * 4;
    float4 s = make_float4(0.f, 0.f, 0.f, 0.f);
    float4 q = make_float4(0.f, 0.f, 0.f, 0.f);
#pragma unroll
    for (int it = 0; it < 16; it++) {
        float4 v = *(const float4*)(p + (size_t)it * 8 * COUT);
        s.x += v.x; s.y += v.y; s.z += v.z; s.w += v.w;
        q.x = fmaf(v.x, v.x, q.x);
        q.y = fmaf(v.y, v.y, q.y);
        q.z = fmaf(v.z, v.z, q.z);
        q.w = fmaf(v.w, v.w, q.w);
    }
    reds[r][cg] = s;
    redq[r][cg] = q;
    __syncthreads();
    if (r == 0) {
        float4 ts = reds[0][cg], tq = redq[0][cg];
#pragma unroll
        for (int j = 1; j < 8; j++) {
            float4 a = reds[j][cg], b2 = redq[j][cg];
            ts.x += a.x; ts.y += a.y; ts.z += a.z; ts.w += a.w;
            tq.x += b2.x; tq.y += b2.y; tq.z += b2.z; tq.w += b2.w;
        }
        *(float4*)&g_fsum[(size_t)blockIdx.x * COUT + cg * 4] = ts;
        *(float4*)&g_fsq [(size_t)blockIdx.x * COUT + cg * 4] = tq;
    }
}

__global__ __launch_bounds__(128)
void finalize_kernel(const float* __restrict__ gamma, const float* __restrict__ beta)
{
    const int c = threadIdx.x;
    double s0 = 0, s1 = 0, s2 = 0, s3 = 0;
    double q0 = 0, q1 = 0, q2 = 0, q3 = 0;
    for (int blk = 0; blk < 1024; blk += 4) {
        s0 += (double)g_fsum[(blk + 0) * COUT + c];
        s1 += (double)g_fsum[(blk + 1) * COUT + c];
        s2 += (double)g_fsum[(blk + 2) * COUT + c];
        s3 += (double)g_fsum[(blk + 3) * COUT + c];
        q0 += (double)g_fsq [(blk + 0) * COUT + c];
        q1 += (double)g_fsq [(blk + 1) * COUT + c];
        q2 += (double)g_fsq [(blk + 2) * COUT + c];
        q3 += (double)g_fsq [(blk + 3) * COUT + c];
    }
    double s = (s0 + s1) + (s2 + s3);
    double q = (q0 + q1) + (q2 + q3);
    const double inv_n = 1.0 / (double)((size_t)BATCH * NPTS);
    double mean = s * inv_n;
    double var  = q * inv_n - mean * mean;
    double scale = (double)gamma[c] / sqrt(var + 1e-5);
    g_scale[c] = (float)scale;
    g_shift[c] = (float)((double)beta[c] - mean * scale);
}

// -------------------------------------------------- gather + maxpool -------
__global__ __launch_bounds__(128)
void maxpool_kernel(const float* __restrict__ h,
                    const int* __restrict__ knn,
                    float* __restrict__ out_feat)
{
    __shared__ int sidx[KNN];
    const int b = blockIdx.x >> 11;
    const int q = blockIdx.x & 2047;
    const int c = threadIdx.x;
    if (c < KNN) sidx[c] = knn[((size_t)b * NPOINT + q) * KNN + c];
    __syncthreads();

    const float sc = g_scale[c], sh = g_shift[c];
    const float* hb = h + (size_t)b * NPTS * COUT;
    float m = -3.4e38f;
#pragma unroll
    for (int k = 0; k < KNN; k++) {
        float v = hb[(size_t)sidx[k] * COUT + c];
        m = fmaxf(m, fmaf(v, sc, sh));
    }
    m = fmaxf(m, 0.0f);
    out_feat[((size_t)b * NPOINT + q) * COUT + c] = m;
}

// ---------------------------------------------------------------------------
extern "C" void kernel_launch(void* const* d_in, const int* in_sizes, int n_in,
                              void* d_out, int out_size)
{
    const float* xyz   = (const float*)d_in[0];
    const float* feat  = (const float*)d_in[1];
    const float* W     = (const float*)d_in[2];
    const float* bias  = (const float*)d_in[3];
    const float* gamma = (const float*)d_in[4];
    const float* beta  = (const float*)d_in[5];

    float* out      = (float*)d_out;
    float* out_xyz  = out;
    float* out_feat = out + ((size_t)out_size - (size_t)BATCH * NPOINT * COUT);

    gemm_kernel<<<(BATCH * NPTS) / 32, 256>>>(feat, W, bias, g_h);
    stats_kernel<<<1024, 256>>>(g_h);
    finalize_kernel<<<1, 128>>>(gamma, beta);
    fps_kernel<<<BATCH * 8, 256>>>(xyz, out_xyz);
    knn_kernel<<<BATCH * 8, 256>>>(xyz, out_xyz, g_knn);
    maxpool_kernel<<<BATCH * NPOINT, 128>>>(g_h, g_knn, out_feat);
    (void)n_in; (void)in_sizes;
}

// round 15
// speedup vs baseline: 1.1815x; 1.1815x over previous
#include <cuda_runtime.h>
#include <math.h>
#include <stdint.h>

#define BATCH  16
#define NPTS   8192
#define NPOINT 2048
#define KNN    16
#define CIN    64
#define COUT   128

// ---------------- scratch (static device globals; no allocation allowed) ----
__device__ float  g_h[(size_t)BATCH * NPTS * COUT];      // conv output, 64 MB
__device__ int    g_knn[(size_t)BATCH * NPOINT * KNN];   // kNN indices
__device__ float  g_fsum[1024 * COUT];                   // stats partials
__device__ float  g_fsq [1024 * COUT];
__device__ float  g_scale[COUT];
__device__ float  g_shift[COUT];

// -------------------------------------------------- f32x2 packed helpers ---
// Per-half IEEE RN semantics == scalar ops -> bit-identical results.
__device__ __forceinline__ unsigned long long pk2(float lo, float hi) {
    unsigned long long r;
    asm("mov.b64 %0, {%1, %2};" : "=l"(r) : "f"(lo), "f"(hi));
    return r;
}
__device__ __forceinline__ void upk2(unsigned long long v, float& lo, float& hi) {
    asm("mov.b64 {%0, %1}, %2;" : "=f"(lo), "=f"(hi) : "l"(v));
}
__device__ __forceinline__ unsigned long long add2(unsigned long long a,
                                                   unsigned long long b) {
    unsigned long long r;
    asm("add.rn.f32x2 %0, %1, %2;" : "=l"(r) : "l"(a), "l"(b));
    return r;
}
__device__ __forceinline__ unsigned long long mul2(unsigned long long a,
                                                   unsigned long long b) {
    unsigned long long r;
    asm("mul.rn.f32x2 %0, %1, %2;" : "=l"(r) : "l"(a), "l"(b));
    return r;
}
__device__ __forceinline__ unsigned long long fma2(unsigned long long a,
                                                   unsigned long long b,
                                                   unsigned long long c) {
    unsigned long long r;
    asm("fma.rn.f32x2 %0, %1, %2, %3;" : "=l"(r) : "l"(a), "l"(b), "l"(c));
    return r;
}

// ---------------------------------------------------------------- FPS ------
// One CTA per batch, 1024 threads, 8 points/thread as 4 f32x2 pairs.
// Per iteration: packed dist update (add2/mul2/fma2 -> bit-identical to the
// reference sub/mul/fma/fma contraction; sub == add of negated centroid,
// exact) -> scalar fminf + FMNMX-tree thread argmax (first-occurrence) ->
// warp REDUX -> lane0 STS (double-buffered) -> ONE __syncthreads -> all warps
// redundantly REDUX the 32 warp winners -> far known everywhere; centroid
// coords read from SMEM. Output deferred via hist.
// Tie rule: max value then MIN index == jnp.argmax first-occurrence.
#define FPS_SMEM_BYTES (3 * NPTS * 4 + 2 * 32 * 4 + 2 * 32 * 4 + NPOINT * 4)

__global__ __launch_bounds__(1024, 1)
void fps_kernel(const float* __restrict__ xyz, float* __restrict__ out_xyz)
{
    extern __shared__ float smem[];
    float*    sx   = smem;
    float*    sy   = sx + NPTS;
    float*    sz   = sy + NPTS;
    unsigned* wv   = (unsigned*)(sz + NPTS);   // [2][32] warp maxima (bits)
    int*      wi   = (int*)(wv + 64);          // [2][32] warp argmax indices
    int*      hist = (int*)(wi + 64);          // [NPOINT] chosen indices

    const int tid  = threadIdx.x;
    const int lane = tid & 31;
    const int warp = tid >> 5;

    const float* base = xyz + (size_t)blockIdx.x * NPTS * 3;
    for (int j = tid; j < NPTS * 3; j += 1024) {
        float v = base[j];
        int p = j / 3, d = j - 3 * p;
        (d == 0 ? sx : (d == 1 ? sy : sz))[p] = v;
    }
    __syncthreads();

    // 8 points/thread packed into 4 f32x2 pairs; pair j holds k=2j (lo), 2j+1 (hi)
    unsigned long long PX[4], PY[4], PZ[4];
    float dist[8];
#pragma unroll
    for (int j = 0; j < 4; j++) {
        int p0 = tid + (2 * j) * 1024;
        int p1 = tid + (2 * j + 1) * 1024;
        PX[j] = pk2(sx[p0], sx[p1]);
        PY[j] = pk2(sy[p0], sy[p1]);
        PZ[j] = pk2(sz[p0], sz[p1]);
        dist[2 * j] = 1e10f; dist[2 * j + 1] = 1e10f;
    }

    int far = 0;

    for (int i = 0; i < NPOINT; i++) {
        if (tid == 0) hist[i] = far;
        const float cx = sx[far], cy = sy[far], cz = sz[far];
        const unsigned long long ncx = pk2(-cx, -cx);
        const unsigned long long ncy = pk2(-cy, -cy);
        const unsigned long long ncz = pk2(-cz, -cz);

        float nd[8];
#pragma unroll
        for (int j = 0; j < 4; j++) {
            unsigned long long dx = add2(PX[j], ncx);   // px - cx (exact)
            unsigned long long dy = add2(PY[j], ncy);
            unsigned long long dz = add2(PZ[j], ncz);
            unsigned long long d  = mul2(dx, dx);       // dx*dx
            d = fma2(dy, dy, d);                        // fmaf(dy,dy,.)
            d = fma2(dz, dz, d);                        // fmaf(dz,dz,.)
            float d0, d1; upk2(d, d0, d1);
            nd[2 * j]     = fminf(dist[2 * j],     d0);
            nd[2 * j + 1] = fminf(dist[2 * j + 1], d1);
            dist[2 * j]     = nd[2 * j];
            dist[2 * j + 1] = nd[2 * j + 1];
        }
        // 3-level max tree
        float m01 = fmaxf(nd[0], nd[1]), m23 = fmaxf(nd[2], nd[3]);
        float m45 = fmaxf(nd[4], nd[5]), m67 = fmaxf(nd[6], nd[7]);
        float m03 = fmaxf(m01, m23),     m47 = fmaxf(m45, m67);
        float m   = fmaxf(m03, m47);
        // smallest k attaining the max (descending scan -> first occurrence)
        int bi = tid;
#pragma unroll
        for (int k = 7; k >= 1; k--)
            if (nd[k] == m) bi = tid + k * 1024;
        if (nd[0] == m) bi = tid;

        // warp argmax via REDUX (dist >= 0: float order == unsigned order)
        unsigned vb   = __float_as_uint(m);
        unsigned wmax = __reduce_max_sync(0xffffffffu, vb);
        unsigned cand = (vb == wmax) ? (unsigned)bi : 0x7fffffffu;
        unsigned widx = __reduce_min_sync(0xffffffffu, cand);

        const int buf = (i & 1) * 32;
        if (lane == 0) { wv[buf + warp] = wmax; wi[buf + warp] = (int)widx; }
        __syncthreads();

        unsigned v2   = wv[buf + lane];
        unsigned i2   = (unsigned)wi[buf + lane];
        unsigned gmax = __reduce_max_sync(0xffffffffu, v2);
        unsigned c2   = (v2 == gmax) ? i2 : 0x7fffffffu;
        far = (int)__reduce_min_sync(0xffffffffu, c2);
    }

    __syncthreads();
    float* oxyz = out_xyz + (size_t)blockIdx.x * NPOINT * 3;
    for (int i = tid; i < NPOINT; i += 1024) {
        int f = hist[i];
        oxyz[i * 3 + 0] = sx[f];
        oxyz[i * 3 + 1] = sy[f];
        oxyz[i * 3 + 2] = sz[f];
    }
}

// ---------------------------------------------------------------- kNN ------
// 128 blocks x 256 threads; one query per thread; float4 candidate tile in
// SMEM. Register-resident unsorted top-K tournament (no dynamic indexing).
// Eviction = lexicographic-largest (dist, idx); strict '<' entry; final set
// equals lax.top_k's K-smallest-by-(value,index) set (order irrelevant).
#define TS 2048

__global__ __launch_bounds__(256)
void knn_kernel(const float* __restrict__ xyz,
                const float* __restrict__ new_xyz,
                int* __restrict__ knn_out)
{
    __shared__ float4 sp[TS];
    const int b = blockIdx.x >> 3;
    const int q = ((blockIdx.x & 7) << 8) + threadIdx.x;

    const float* nb = new_xyz + ((size_t)b * NPOINT + q) * 3;
    const float qx = nb[0], qy = nb[1], qz = nb[2];

    float kd[KNN]; int ki[KNN];
#pragma unroll
    for (int k = 0; k < KNN; k++) { kd[k] = 3.4e38f; ki[k] = -1; }
    float worstd = 3.4e38f;
    int   wslot  = 0;

    const float* base = xyz + (size_t)b * NPTS * 3;
    for (int t = 0; t < NPTS; t += TS) {
        __syncthreads();
        for (int p = threadIdx.x; p < TS; p += 256) {
            const float* src = base + (size_t)(t + p) * 3;
            sp[p] = make_float4(src[0], src[1], src[2], 0.0f);
        }
        __syncthreads();
#pragma unroll 4
        for (int j = 0; j < TS; j++) {
            float4 c = sp[j];
            float dx = qx - c.x, dy = qy - c.y, dz = qz - c.z;
            float d = dx * dx;
            d = fmaf(dy, dy, d);
            d = fmaf(dz, dz, d);
            if (d < worstd) {
                const int jj = t + j;
#pragma unroll
                for (int s = 0; s < KNN; s++)
                    if (s == wslot) { kd[s] = d; ki[s] = jj; }
                float wd = kd[0]; int wix = ki[0]; int ws = 0;
#pragma unroll
                for (int s = 1; s < KNN; s++) {
                    bool takes = (kd[s] > wd) || (kd[s] == wd && ki[s] > wix);
                    if (takes) { wd = kd[s]; wix = ki[s]; ws = s; }
                }
                worstd = wd; wslot = ws;
            }
        }
    }
    int* o = knn_out + ((size_t)b * NPOINT + q) * KNN;
#pragma unroll
    for (int k = 0; k < KNN; k++) o[k] = ki[k];
}

// ---------------------------------------------------------------- GEMM -----
__global__ __launch_bounds__(256)
void gemm_kernel(const float* __restrict__ feat,
                 const float* __restrict__ W,
                 const float* __restrict__ bias,
                 float* __restrict__ h)
{
    __shared__ float Wt[CIN * COUT];
    __shared__ float sf[32 * CIN];
    const int tid = threadIdx.x;

    for (int j = tid; j < CIN * COUT; j += 256) {
        int c = j >> 6, k = j & 63;
        Wt[k * COUT + c] = W[j];
    }
    const size_t row0 = (size_t)blockIdx.x * 32;
    const float* fb = feat + row0 * CIN;
    for (int j = tid; j < 32 * CIN; j += 256) sf[j] = fb[j];
    __syncthreads();

    const int cg = tid & 31;
    const int rg = tid >> 5;

    float acc[4][4];
#pragma unroll
    for (int r = 0; r < 4; r++)
#pragma unroll
        for (int c = 0; c < 4; c++) acc[r][c] = 0.0f;

#pragma unroll 8
    for (int k = 0; k < CIN; k++) {
        float4 wv = *(const float4*)&Wt[k * COUT + cg * 4];
        float f0 = sf[(rg * 4 + 0) * CIN + k];
        float f1 = sf[(rg * 4 + 1) * CIN + k];
        float f2 = sf[(rg * 4 + 2) * CIN + k];
        float f3 = sf[(rg * 4 + 3) * CIN + k];
        acc[0][0] = fmaf(f0, wv.x, acc[0][0]);
        acc[0][1] = fmaf(f0, wv.y, acc[0][1]);
        acc[0][2] = fmaf(f0, wv.z, acc[0][2]);
        acc[0][3] = fmaf(f0, wv.w, acc[0][3]);
        acc[1][0] = fmaf(f1, wv.x, acc[1][0]);
        acc[1][1] = fmaf(f1, wv.y, acc[1][1]);
        acc[1][2] = fmaf(f1, wv.z, acc[1][2]);
        acc[1][3] = fmaf(f1, wv.w, acc[1][3]);
        acc[2][0] = fmaf(f2, wv.x, acc[2][0]);
        acc[2][1] = fmaf(f2, wv.y, acc[2][1]);
        acc[2][2] = fmaf(f2, wv.z, acc[2][2]);
        acc[2][3] = fmaf(f2, wv.w, acc[2][3]);
        acc[3][0] = fmaf(f3, wv.x, acc[3][0]);
        acc[3][1] = fmaf(f3, wv.y, acc[3][1]);
        acc[3][2] = fmaf(f3, wv.z, acc[3][2]);
        acc[3][3] = fmaf(f3, wv.w, acc[3][3]);
    }
    const float4 bb = *(const float4*)&bias[cg * 4];
#pragma unroll
    for (int r = 0; r < 4; r++) {
        float4 o;
        o.x = acc[r][0] + bb.x;
        o.y = acc[r][1] + bb.y;
        o.z = acc[r][2] + bb.z;
        o.w = acc[r][3] + bb.w;
        *(float4*)&h[(row0 + rg * 4 + r) * COUT + cg * 4] = o;
    }
}

// ----------------------------------------------------------- BN stats ------
__global__ __launch_bounds__(256)
void stats_kernel(const float* __restrict__ h)
{
    __shared__ float4 reds[8][32];
    __shared__ float4 redq[8][32];
    const int tid = threadIdx.x;
    const int cg  = tid & 31;
    const int r   = tid >> 5;

    const float* p = h + ((size_t)blockIdx.x * 128 + r) * COUT + cg * 4;
    float4 s = make_float4(0.f, 0.f, 0.f, 0.f);
    float4 q = make_float4(0.f, 0.f, 0.f, 0.f);
#pragma unroll
    for (int it = 0; it < 16; it++) {
        float4 v = *(const float4*)(p + (size_t)it * 8 * COUT);
        s.x += v.x; s.y += v.y; s.z += v.z; s.w += v.w;
        q.x = fmaf(v.x, v.x, q.x);
        q.y = fmaf(v.y, v.y, q.y);
        q.z = fmaf(v.z, v.z, q.z);
        q.w = fmaf(v.w, v.w, q.w);
    }
    reds[r][cg] = s;
    redq[r][cg] = q;
    __syncthreads();
    if (r == 0) {
        float4 ts = reds[0][cg], tq = redq[0][cg];
#pragma unroll
        for (int j = 1; j < 8; j++) {
            float4 a = reds[j][cg], b2 = redq[j][cg];
            ts.x += a.x; ts.y += a.y; ts.z += a.z; ts.w += a.w;
            tq.x += b2.x; tq.y += b2.y; tq.z += b2.z; tq.w += b2.w;
        }
        *(float4*)&g_fsum[(size_t)blockIdx.x * COUT + cg * 4] = ts;
        *(float4*)&g_fsq [(size_t)blockIdx.x * COUT + cg * 4] = tq;
    }
}

__global__ __launch_bounds__(128)
void finalize_kernel(const float* __restrict__ gamma, const float* __restrict__ beta)
{
    const int c = threadIdx.x;
    double s0 = 0, s1 = 0, s2 = 0, s3 = 0;
    double q0 = 0, q1 = 0, q2 = 0, q3 = 0;
    for (int blk = 0; blk < 1024; blk += 4) {
        s0 += (double)g_fsum[(blk + 0) * COUT + c];
        s1 += (double)g_fsum[(blk + 1) * COUT + c];
        s2 += (double)g_fsum[(blk + 2) * COUT + c];
        s3 += (double)g_fsum[(blk + 3) * COUT + c];
        q0 += (double)g_fsq [(blk + 0) * COUT + c];
        q1 += (double)g_fsq [(blk + 1) * COUT + c];
        q2 += (double)g_fsq [(blk + 2) * COUT + c];
        q3 += (double)g_fsq [(blk + 3) * COUT + c];
    }
    double s = (s0 + s1) + (s2 + s3);
    double q = (q0 + q1) + (q2 + q3);
    const double inv_n = 1.0 / (double)((size_t)BATCH * NPTS);
    double mean = s * inv_n;
    double var  = q * inv_n - mean * mean;
    double scale = (double)gamma[c] / sqrt(var + 1e-5);
    g_scale[c] = (float)scale;
    g_shift[c] = (float)((double)beta[c] - mean * scale);
}

// -------------------------------------------------- gather + maxpool -------
__global__ __launch_bounds__(128)
void maxpool_kernel(const float* __restrict__ h,
                    const int* __restrict__ knn,
                    float* __restrict__ out_feat)
{
    __shared__ int sidx[KNN];
    const int b = blockIdx.x >> 11;
    const int q = blockIdx.x & 2047;
    const int c = threadIdx.x;
    if (c < KNN) sidx[c] = knn[((size_t)b * NPOINT + q) * KNN + c];
    __syncthreads();

    const float sc = g_scale[c], sh = g_shift[c];
    const float* hb = h + (size_t)b * NPTS * COUT;
    float m = -3.4e38f;
#pragma unroll
    for (int k = 0; k < KNN; k++) {
        float v = hb[(size_t)sidx[k] * COUT + c];
        m = fmaxf(m, fmaf(v, sc, sh));
    }
    m = fmaxf(m, 0.0f);
    out_feat[((size_t)b * NPOINT + q) * COUT + c] = m;
}

// ---------------------------------------------------------------------------
extern "C" void kernel_launch(void* const* d_in, const int* in_sizes, int n_in,
                              void* d_out, int out_size)
{
    const float* xyz   = (const float*)d_in[0];
    const float* feat  = (const float*)d_in[1];
    const float* W     = (const float*)d_in[2];
    const float* bias  = (const float*)d_in[3];
    const float* gamma = (const float*)d_in[4];
    const float* beta  = (const float*)d_in[5];

    float* out      = (float*)d_out;
    float* out_xyz  = out;
    float* out_feat = out + ((size_t)out_size - (size_t)BATCH * NPOINT * COUT);

    cudaFuncSetAttribute(fps_kernel, cudaFuncAttributeMaxDynamicSharedMemorySize,
                         FPS_SMEM_BYTES);

    gemm_kernel<<<(BATCH * NPTS) / 32, 256>>>(feat, W, bias, g_h);
    stats_kernel<<<1024, 256>>>(g_h);
    finalize_kernel<<<1, 128>>>(gamma, beta);
    fps_kernel<<<BATCH, 1024, FPS_SMEM_BYTES>>>(xyz, out_xyz);
    knn_kernel<<<BATCH * 8, 256>>>(xyz, out_xyz, g_knn);
    maxpool_kernel<<<BATCH * NPOINT, 128>>>(g_h, g_knn, out_feat);
    (void)n_in; (void)in_sizes;
}

// round 16
// speedup vs baseline: 1.1984x; 1.0143x over previous
#include <cuda_runtime.h>
#include <math.h>
#include <stdint.h>

#define BATCH  16
#define NPTS   8192
#define NPOINT 2048
#define KNN    16
#define CIN    64
#define COUT   128

// ---------------- scratch (static device globals; no allocation allowed) ----
__device__ float  g_h[(size_t)BATCH * NPTS * COUT];      // conv output, 64 MB
__device__ int    g_knn[(size_t)BATCH * NPOINT * KNN];   // kNN indices
__device__ float  g_fsum[1024 * COUT];                   // stats partials
__device__ float  g_fsq [1024 * COUT];
__device__ float  g_scale[COUT];
__device__ float  g_shift[COUT];

// -------------------------------------------------- f32x2 packed helpers ---
// Per-half IEEE RN semantics == scalar ops -> bit-identical results.
__device__ __forceinline__ unsigned long long pk2(float lo, float hi) {
    unsigned long long r;
    asm("mov.b64 %0, {%1, %2};" : "=l"(r) : "f"(lo), "f"(hi));
    return r;
}
__device__ __forceinline__ void upk2(unsigned long long v, float& lo, float& hi) {
    asm("mov.b64 {%0, %1}, %2;" : "=f"(lo), "=f"(hi) : "l"(v));
}
__device__ __forceinline__ unsigned long long add2(unsigned long long a,
                                                   unsigned long long b) {
    unsigned long long r;
    asm("add.rn.f32x2 %0, %1, %2;" : "=l"(r) : "l"(a), "l"(b));
    return r;
}
__device__ __forceinline__ unsigned long long mul2(unsigned long long a,
                                                   unsigned long long b) {
    unsigned long long r;
    asm("mul.rn.f32x2 %0, %1, %2;" : "=l"(r) : "l"(a), "l"(b));
    return r;
}
__device__ __forceinline__ unsigned long long fma2(unsigned long long a,
                                                   unsigned long long b,
                                                   unsigned long long c) {
    unsigned long long r;
    asm("fma.rn.f32x2 %0, %1, %2, %3;" : "=l"(r) : "l"(a), "l"(b), "l"(c));
    return r;
}

// ---------------------------------------------------------------- FPS ------
// One CTA per batch, 256 threads (8 warps), 32 points/thread as 16 f32x2
// pairs. Rationale: per-SMSP compute issue is invariant in points/thread, but
// warp-collective costs (REDUX, barrier skew, redundant tail) scale with warp
// count — so use the fewest warps that fit registers.
// Per iteration: packed dist update (bit-identical to reference
// sub/mul/fma/fma; sub == add of negation, exact) -> in-place fminf ->
// 5-level FMNMX tree -> descending-k equality scan (first occurrence) ->
// warp REDUX argmax -> lane0 STS (double-buffered, 8 slots) -> ONE
// __syncthreads -> all 8 warps REDUX the 8 winners (lane&7 replication:
// max/min unaffected) -> far known everywhere; coords from SMEM mirror.
// Output deferred via hist. Tie rule: max value then MIN index == jnp.argmax.
#define FPS_SMEM_BYTES (3 * NPTS * 4 + 2 * 8 * 4 + 2 * 8 * 4 + NPOINT * 4)
#define PPT 32
#define FPT 256   // fps threads

__global__ __launch_bounds__(FPT, 1)
void fps_kernel(const float* __restrict__ xyz, float* __restrict__ out_xyz)
{
    extern __shared__ float smem[];
    float*    sx   = smem;
    float*    sy   = sx + NPTS;
    float*    sz   = sy + NPTS;
    unsigned* wv   = (unsigned*)(sz + NPTS);   // [2][8] warp maxima (bits)
    int*      wi   = (int*)(wv + 16);          // [2][8] warp argmax indices
    int*      hist = (int*)(wi + 16);          // [NPOINT] chosen indices

    const int tid  = threadIdx.x;
    const int lane = tid & 31;
    const int warp = tid >> 5;

    const float* base = xyz + (size_t)blockIdx.x * NPTS * 3;
    for (int j = tid; j < NPTS * 3; j += FPT) {
        float v = base[j];
        int p = j / 3, d = j - 3 * p;
        (d == 0 ? sx : (d == 1 ? sy : sz))[p] = v;
    }
    __syncthreads();

    // 32 points/thread packed into 16 f32x2 pairs; pair j: k=2j (lo), 2j+1 (hi)
    unsigned long long PX[16], PY[16], PZ[16];
    float dist[PPT];
#pragma unroll
    for (int j = 0; j < 16; j++) {
        int p0 = tid + (2 * j) * FPT;
        int p1 = tid + (2 * j + 1) * FPT;
        PX[j] = pk2(sx[p0], sx[p1]);
        PY[j] = pk2(sy[p0], sy[p1]);
        PZ[j] = pk2(sz[p0], sz[p1]);
        dist[2 * j] = 1e10f; dist[2 * j + 1] = 1e10f;
    }

    int far = 0;

    for (int i = 0; i < NPOINT; i++) {
        if (tid == 0) hist[i] = far;
        const float cx = sx[far], cy = sy[far], cz = sz[far];
        const unsigned long long ncx = pk2(-cx, -cx);
        const unsigned long long ncy = pk2(-cy, -cy);
        const unsigned long long ncz = pk2(-cz, -cz);

#pragma unroll
        for (int j = 0; j < 16; j++) {
            unsigned long long dx = add2(PX[j], ncx);   // px - cx (exact)
            unsigned long long dy = add2(PY[j], ncy);
            unsigned long long dz = add2(PZ[j], ncz);
            unsigned long long d  = mul2(dx, dx);
            d = fma2(dy, dy, d);
            d = fma2(dz, dz, d);
            float d0, d1; upk2(d, d0, d1);
            dist[2 * j]     = fminf(dist[2 * j],     d0);
            dist[2 * j + 1] = fminf(dist[2 * j + 1], d1);
        }
        // 5-level max tree over dist[32]
        float t16[16];
#pragma unroll
        for (int j = 0; j < 16; j++) t16[j] = fmaxf(dist[2 * j], dist[2 * j + 1]);
        float t8[8];
#pragma unroll
        for (int j = 0; j < 8; j++) t8[j] = fmaxf(t16[2 * j], t16[2 * j + 1]);
        float t4a = fmaxf(t8[0], t8[1]), t4b = fmaxf(t8[2], t8[3]);
        float t4c = fmaxf(t8[4], t8[5]), t4d = fmaxf(t8[6], t8[7]);
        float m = fmaxf(fmaxf(t4a, t4b), fmaxf(t4c, t4d));

        // smallest k attaining the max (descending scan -> first occurrence)
        int bi = tid;
#pragma unroll
        for (int k = PPT - 1; k >= 1; k--)
            if (dist[k] == m) bi = tid + k * FPT;
        if (dist[0] == m) bi = tid;

        // warp argmax via REDUX (dist >= 0: float order == unsigned order)
        unsigned vb   = __float_as_uint(m);
        unsigned wmax = __reduce_max_sync(0xffffffffu, vb);
        unsigned cand = (vb == wmax) ? (unsigned)bi : 0x7fffffffu;
        unsigned widx = __reduce_min_sync(0xffffffffu, cand);

        const int buf = (i & 1) * 8;
        if (lane == 0) { wv[buf + warp] = wmax; wi[buf + warp] = (int)widx; }
        __syncthreads();

        // all 8 warps reduce the 8 winners; lane&7 replicates 4x (max/min ok)
        unsigned v2   = wv[buf + (lane & 7)];
        unsigned i2   = (unsigned)wi[buf + (lane & 7)];
        unsigned gmax = __reduce_max_sync(0xffffffffu, v2);
        unsigned c2   = (v2 == gmax) ? i2 : 0x7fffffffu;
        far = (int)__reduce_min_sync(0xffffffffu, c2);
    }

    __syncthreads();
    float* oxyz = out_xyz + (size_t)blockIdx.x * NPOINT * 3;
    for (int i = tid; i < NPOINT; i += FPT) {
        int f = hist[i];
        oxyz[i * 3 + 0] = sx[f];
        oxyz[i * 3 + 1] = sy[f];
        oxyz[i * 3 + 2] = sz[f];
    }
}

// ---------------------------------------------------------------- kNN ------
// 128 blocks x 256 threads; one query per thread; float4 candidate tile in
// SMEM. Register-resident unsorted top-K tournament (no dynamic indexing).
// Eviction = lexicographic-largest (dist, idx); strict '<' entry; final set
// equals lax.top_k's K-smallest-by-(value,index) set (order irrelevant).
#define TS 2048

__global__ __launch_bounds__(256)
void knn_kernel(const float* __restrict__ xyz,
                const float* __restrict__ new_xyz,
                int* __restrict__ knn_out)
{
    __shared__ float4 sp[TS];
    const int b = blockIdx.x >> 3;
    const int q = ((blockIdx.x & 7) << 8) + threadIdx.x;

    const float* nb = new_xyz + ((size_t)b * NPOINT + q) * 3;
    const float qx = nb[0], qy = nb[1], qz = nb[2];

    float kd[KNN]; int ki[KNN];
#pragma unroll
    for (int k = 0; k < KNN; k++) { kd[k] = 3.4e38f; ki[k] = -1; }
    float worstd = 3.4e38f;
    int   wslot  = 0;

    const float* base = xyz + (size_t)b * NPTS * 3;
    for (int t = 0; t < NPTS; t += TS) {
        __syncthreads();
        for (int p = threadIdx.x; p < TS; p += 256) {
            const float* src = base + (size_t)(t + p) * 3;
            sp[p] = make_float4(src[0], src[1], src[2], 0.0f);
        }
        __syncthreads();
#pragma unroll 4
        for (int j = 0; j < TS; j++) {
            float4 c = sp[j];
            float dx = qx - c.x, dy = qy - c.y, dz = qz - c.z;
            float d = dx * dx;
            d = fmaf(dy, dy, d);
            d = fmaf(dz, dz, d);
            if (d < worstd) {
                const int jj = t + j;
#pragma unroll
                for (int s = 0; s < KNN; s++)
                    if (s == wslot) { kd[s] = d; ki[s] = jj; }
                float wd = kd[0]; int wix = ki[0]; int ws = 0;
#pragma unroll
                for (int s = 1; s < KNN; s++) {
                    bool takes = (kd[s] > wd) || (kd[s] == wd && ki[s] > wix);
                    if (takes) { wd = kd[s]; wix = ki[s]; ws = s; }
                }
                worstd = wd; wslot = ws;
            }
        }
    }
    int* o = knn_out + ((size_t)b * NPOINT + q) * KNN;
#pragma unroll
    for (int k = 0; k < KNN; k++) o[k] = ki[k];
}

// ---------------------------------------------------------------- GEMM -----
__global__ __launch_bounds__(256)
void gemm_kernel(const float* __restrict__ feat,
                 const float* __restrict__ W,
                 const float* __restrict__ bias,
                 float* __restrict__ h)
{
    __shared__ float Wt[CIN * COUT];
    __shared__ float sf[32 * CIN];
    const int tid = threadIdx.x;

    for (int j = tid; j < CIN * COUT; j += 256) {
        int c = j >> 6, k = j & 63;
        Wt[k * COUT + c] = W[j];
    }
    const size_t row0 = (size_t)blockIdx.x * 32;
    const float* fb = feat + row0 * CIN;
    for (int j = tid; j < 32 * CIN; j += 256) sf[j] = fb[j];
    __syncthreads();

    const int cg = tid & 31;
    const int rg = tid >> 5;

    float acc[4][4];
#pragma unroll
    for (int r = 0; r < 4; r++)
#pragma unroll
        for (int c = 0; c < 4; c++) acc[r][c] = 0.0f;

#pragma unroll 8
    for (int k = 0; k < CIN; k++) {
        float4 wv = *(const float4*)&Wt[k * COUT + cg * 4];
        float f0 = sf[(rg * 4 + 0) * CIN + k];
        float f1 = sf[(rg * 4 + 1) * CIN + k];
        float f2 = sf[(rg * 4 + 2) * CIN + k];
        float f3 = sf[(rg * 4 + 3) * CIN + k];
        acc[0][0] = fmaf(f0, wv.x, acc[0][0]);
        acc[0][1] = fmaf(f0, wv.y, acc[0][1]);
        acc[0][2] = fmaf(f0, wv.z, acc[0][2]);
        acc[0][3] = fmaf(f0, wv.w, acc[0][3]);
        acc[1][0] = fmaf(f1, wv.x, acc[1][0]);
        acc[1][1] = fmaf(f1, wv.y, acc[1][1]);
        acc[1][2] = fmaf(f1, wv.z, acc[1][2]);
        acc[1][3] = fmaf(f1, wv.w, acc[1][3]);
        acc[2][0] = fmaf(f2, wv.x, acc[2][0]);
        acc[2][1] = fmaf(f2, wv.y, acc[2][1]);
        acc[2][2] = fmaf(f2, wv.z, acc[2][2]);
        acc[2][3] = fmaf(f2, wv.w, acc[2][3]);
        acc[3][0] = fmaf(f3, wv.x, acc[3][0]);
        acc[3][1] = fmaf(f3, wv.y, acc[3][1]);
        acc[3][2] = fmaf(f3, wv.z, acc[3][2]);
        acc[3][3] = fmaf(f3, wv.w, acc[3][3]);
    }
    const float4 bb = *(const float4*)&bias[cg * 4];
#pragma unroll
    for (int r = 0; r < 4; r++) {
        float4 o;
        o.x = acc[r][0] + bb.x;
        o.y = acc[r][1] + bb.y;
        o.z = acc[r][2] + bb.z;
        o.w = acc[r][3] + bb.w;
        *(float4*)&h[(row0 + rg * 4 + r) * COUT + cg * 4] = o;
    }
}

// ----------------------------------------------------------- BN stats ------
__global__ __launch_bounds__(256)
void stats_kernel(const float* __restrict__ h)
{
    __shared__ float4 reds[8][32];
    __shared__ float4 redq[8][32];
    const int tid = threadIdx.x;
    const int cg  = tid & 31;
    const int r   = tid >> 5;

    const float* p = h + ((size_t)blockIdx.x * 128 + r) * COUT + cg * 4;
    float4 s = make_float4(0.f, 0.f, 0.f, 0.f);
    float4 q = make_float4(0.f, 0.f, 0.f, 0.f);
#pragma unroll
    for (int it = 0; it < 16; it++) {
        float4 v = *(const float4*)(p + (size_t)it * 8 * COUT);
        s.x += v.x; s.y += v.y; s.z += v.z; s.w += v.w;
        q.x = fmaf(v.x, v.x, q.x);
        q.y = fmaf(v.y, v.y, q.y);
        q.z = fmaf(v.z, v.z, q.z);
        q.w = fmaf(v.w, v.w, q.w);
    }
    reds[r][cg] = s;
    redq[r][cg] = q;
    __syncthreads();
    if (r == 0) {
        float4 ts = reds[0][cg], tq = redq[0][cg];
#pragma unroll
        for (int j = 1; j < 8; j++) {
            float4 a = reds[j][cg], b2 = redq[j][cg];
            ts.x += a.x; ts.y += a.y; ts.z += a.z; ts.w += a.w;
            tq.x += b2.x; tq.y += b2.y; tq.z += b2.z; tq.w += b2.w;
        }
        *(float4*)&g_fsum[(size_t)blockIdx.x * COUT + cg * 4] = ts;
        *(float4*)&g_fsq [(size_t)blockIdx.x * COUT + cg * 4] = tq;
    }
}

__global__ __launch_bounds__(128)
void finalize_kernel(const float* __restrict__ gamma, const float* __restrict__ beta)
{
    const int c = threadIdx.x;
    double s0 = 0, s1 = 0, s2 = 0, s3 = 0;
    double q0 = 0, q1 = 0, q2 = 0, q3 = 0;
    for (int blk = 0; blk < 1024; blk += 4) {
        s0 += (double)g_fsum[(blk + 0) * COUT + c];
        s1 += (double)g_fsum[(blk + 1) * COUT + c];
        s2 += (double)g_fsum[(blk + 2) * COUT + c];
        s3 += (double)g_fsum[(blk + 3) * COUT + c];
        q0 += (double)g_fsq [(blk + 0) * COUT + c];
        q1 += (double)g_fsq [(blk + 1) * COUT + c];
        q2 += (double)g_fsq [(blk + 2) * COUT + c];
        q3 += (double)g_fsq [(blk + 3) * COUT + c];
    }
    double s = (s0 + s1) + (s2 + s3);
    double q = (q0 + q1) + (q2 + q3);
    const double inv_n = 1.0 / (double)((size_t)BATCH * NPTS);
    double mean = s * inv_n;
    double var  = q * inv_n - mean * mean;
    double scale = (double)gamma[c] / sqrt(var + 1e-5);
    g_scale[c] = (float)scale;
    g_shift[c] = (float)((double)beta[c] - mean * scale);
}

// -------------------------------------------------- gather + maxpool -------
__global__ __launch_bounds__(128)
void maxpool_kernel(const float* __restrict__ h,
                    const int* __restrict__ knn,
                    float* __restrict__ out_feat)
{
    __shared__ int sidx[KNN];
    const int b = blockIdx.x >> 11;
    const int q = blockIdx.x & 2047;
    const int c = threadIdx.x;
    if (c < KNN) sidx[c] = knn[((size_t)b * NPOINT + q) * KNN + c];
    __syncthreads();

    const float sc = g_scale[c], sh = g_shift[c];
    const float* hb = h + (size_t)b * NPTS * COUT;
    float m = -3.4e38f;
#pragma unroll
    for (int k = 0; k < KNN; k++) {
        float v = hb[(size_t)sidx[k] * COUT + c];
        m = fmaxf(m, fmaf(v, sc, sh));
    }
    m = fmaxf(m, 0.0f);
    out_feat[((size_t)b * NPOINT + q) * COUT + c] = m;
}

// ---------------------------------------------------------------------------
extern "C" void kernel_launch(void* const* d_in, const int* in_sizes, int n_in,
                              void* d_out, int out_size)
{
    const float* xyz   = (const float*)d_in[0];
    const float* feat  = (const float*)d_in[1];
    const float* W     = (const float*)d_in[2];
    const float* bias  = (const float*)d_in[3];
    const float* gamma = (const float*)d_in[4];
    const float* beta  = (const float*)d_in[5];

    float* out      = (float*)d_out;
    float* out_xyz  = out;
    float* out_feat = out + ((size_t)out_size - (size_t)BATCH * NPOINT * COUT);

    cudaFuncSetAttribute(fps_kernel, cudaFuncAttributeMaxDynamicSharedMemorySize,
                         FPS_SMEM_BYTES);

    gemm_kernel<<<(BATCH * NPTS) / 32, 256>>>(feat, W, bias, g_h);
    stats_kernel<<<1024, 256>>>(g_h);
    finalize_kernel<<<1, 128>>>(gamma, beta);
    fps_kernel<<<BATCH, FPT, FPS_SMEM_BYTES>>>(xyz, out_xyz);
    knn_kernel<<<BATCH * 8, 256>>>(xyz, out_xyz, g_knn);
    maxpool_kernel<<<BATCH * NPOINT, 128>>>(g_h, g_knn, out_feat);
    (void)n_in; (void)in_sizes;
}

// round 17
// speedup vs baseline: 1.3269x; 1.1072x over previous
#include <cuda_runtime.h>
#include <math.h>
#include <stdint.h>

#define BATCH  16
#define NPTS   8192
#define NPOINT 2048
#define KNN    16
#define CIN    64
#define COUT   128

// ---------------- scratch (static device globals; no allocation allowed) ----
__device__ float  g_h[(size_t)BATCH * NPTS * COUT];      // conv output, 64 MB
__device__ int    g_knn[(size_t)BATCH * NPOINT * KNN];   // kNN indices
__device__ float  g_fsum[1024 * COUT];                   // stats partials
__device__ float  g_fsq [1024 * COUT];
__device__ float  g_scale[COUT];
__device__ float  g_shift[COUT];

// -------------------------------------------------- f32x2 packed helpers ---
__device__ __forceinline__ unsigned long long pk2(float lo, float hi) {
    unsigned long long r;
    asm("mov.b64 %0, {%1, %2};" : "=l"(r) : "f"(lo), "f"(hi));
    return r;
}
__device__ __forceinline__ void upk2(unsigned long long v, float& lo, float& hi) {
    asm("mov.b64 {%0, %1}, %2;" : "=f"(lo), "=f"(hi) : "l"(v));
}
__device__ __forceinline__ unsigned long long add2(unsigned long long a,
                                                   unsigned long long b) {
    unsigned long long r;
    asm("add.rn.f32x2 %0, %1, %2;" : "=l"(r) : "l"(a), "l"(b));
    return r;
}
__device__ __forceinline__ unsigned long long mul2(unsigned long long a,
                                                   unsigned long long b) {
    unsigned long long r;
    asm("mul.rn.f32x2 %0, %1, %2;" : "=l"(r) : "l"(a), "l"(b));
    return r;
}
__device__ __forceinline__ unsigned long long fma2(unsigned long long a,
                                                   unsigned long long b,
                                                   unsigned long long c) {
    unsigned long long r;
    asm("fma.rn.f32x2 %0, %1, %2, %3;" : "=l"(r) : "l"(a), "l"(b), "l"(c));
    return r;
}

// ---------------------------------------------------------------- FPS ------
// One CTA per batch, 256 threads (8 warps), 32 points/thread as 16 f32x2
// pairs. (Unchanged from R16: measured 983us.)
#define FPS_SMEM_BYTES (3 * NPTS * 4 + 2 * 8 * 4 + 2 * 8 * 4 + NPOINT * 4)
#define PPT 32
#define FPT 256

__global__ __launch_bounds__(FPT, 1)
void fps_kernel(const float* __restrict__ xyz, float* __restrict__ out_xyz)
{
    extern __shared__ float smem[];
    float*    sx   = smem;
    float*    sy   = sx + NPTS;
    float*    sz   = sy + NPTS;
    unsigned* wv   = (unsigned*)(sz + NPTS);   // [2][8] warp maxima (bits)
    int*      wi   = (int*)(wv + 16);          // [2][8] warp argmax indices
    int*      hist = (int*)(wi + 16);          // [NPOINT] chosen indices

    const int tid  = threadIdx.x;
    const int lane = tid & 31;
    const int warp = tid >> 5;

    const float* base = xyz + (size_t)blockIdx.x * NPTS * 3;
    for (int j = tid; j < NPTS * 3; j += FPT) {
        float v = base[j];
        int p = j / 3, d = j - 3 * p;
        (d == 0 ? sx : (d == 1 ? sy : sz))[p] = v;
    }
    __syncthreads();

    unsigned long long PX[16], PY[16], PZ[16];
    float dist[PPT];
#pragma unroll
    for (int j = 0; j < 16; j++) {
        int p0 = tid + (2 * j) * FPT;
        int p1 = tid + (2 * j + 1) * FPT;
        PX[j] = pk2(sx[p0], sx[p1]);
        PY[j] = pk2(sy[p0], sy[p1]);
        PZ[j] = pk2(sz[p0], sz[p1]);
        dist[2 * j] = 1e10f; dist[2 * j + 1] = 1e10f;
    }

    int far = 0;

    for (int i = 0; i < NPOINT; i++) {
        if (tid == 0) hist[i] = far;
        const float cx = sx[far], cy = sy[far], cz = sz[far];
        const unsigned long long ncx = pk2(-cx, -cx);
        const unsigned long long ncy = pk2(-cy, -cy);
        const unsigned long long ncz = pk2(-cz, -cz);

#pragma unroll
        for (int j = 0; j < 16; j++) {
            unsigned long long dx = add2(PX[j], ncx);
            unsigned long long dy = add2(PY[j], ncy);
            unsigned long long dz = add2(PZ[j], ncz);
            unsigned long long d  = mul2(dx, dx);
            d = fma2(dy, dy, d);
            d = fma2(dz, dz, d);
            float d0, d1; upk2(d, d0, d1);
            dist[2 * j]     = fminf(dist[2 * j],     d0);
            dist[2 * j + 1] = fminf(dist[2 * j + 1], d1);
        }
        float t16[16];
#pragma unroll
        for (int j = 0; j < 16; j++) t16[j] = fmaxf(dist[2 * j], dist[2 * j + 1]);
        float t8[8];
#pragma unroll
        for (int j = 0; j < 8; j++) t8[j] = fmaxf(t16[2 * j], t16[2 * j + 1]);
        float t4a = fmaxf(t8[0], t8[1]), t4b = fmaxf(t8[2], t8[3]);
        float t4c = fmaxf(t8[4], t8[5]), t4d = fmaxf(t8[6], t8[7]);
        float m = fmaxf(fmaxf(t4a, t4b), fmaxf(t4c, t4d));

        int bi = tid;
#pragma unroll
        for (int k = PPT - 1; k >= 1; k--)
            if (dist[k] == m) bi = tid + k * FPT;
        if (dist[0] == m) bi = tid;

        unsigned vb   = __float_as_uint(m);
        unsigned wmax = __reduce_max_sync(0xffffffffu, vb);
        unsigned cand = (vb == wmax) ? (unsigned)bi : 0x7fffffffu;
        unsigned widx = __reduce_min_sync(0xffffffffu, cand);

        const int buf = (i & 1) * 8;
        if (lane == 0) { wv[buf + warp] = wmax; wi[buf + warp] = (int)widx; }
        __syncthreads();

        unsigned v2   = wv[buf + (lane & 7)];
        unsigned i2   = (unsigned)wi[buf + (lane & 7)];
        unsigned gmax = __reduce_max_sync(0xffffffffu, v2);
        unsigned c2   = (v2 == gmax) ? i2 : 0x7fffffffu;
        far = (int)__reduce_min_sync(0xffffffffu, c2);
    }

    __syncthreads();
    float* oxyz = out_xyz + (size_t)blockIdx.x * NPOINT * 3;
    for (int i = tid; i < NPOINT; i += FPT) {
        int f = hist[i];
        oxyz[i * 3 + 0] = sx[f];
        oxyz[i * 3 + 1] = sy[f];
        oxyz[i * 3 + 2] = sz[f];
    }
}

// ---------------------------------------------------------------- kNN ------
// 128 blocks x 256 threads; one query per thread; float4 candidate tile in
// SMEM. Top-K as 16 packed u64 keys ((distbits<<32)|idx; d>=0 so u64 order ==
// lexicographic (d, idx) order). Insert: 16 PARALLEL predicated replacements
// of the slot whose key == maxkey (idx uniqueness + distinct sentinels =>
// exactly one match), then depth-4 TREE max recompute (~25 cyc latency vs the
// old 16-step serial scan ~300 cyc). Entry test amortized 4-wide:
// min(d0..d3) < worstd gates the rare path (4x fewer branches).
// Semantics: strict '<' entry by value, evict lexicographic-largest (d,idx),
// candidates ascending -> final SET == lax.top_k K-smallest-by-(value,index)
// (order irrelevant: max-pool follows).
#define TS 2048

__device__ __forceinline__ unsigned long long umax64(unsigned long long a,
                                                     unsigned long long b) {
    return a > b ? a : b;
}

__global__ __launch_bounds__(256)
void knn_kernel(const float* __restrict__ xyz,
                const float* __restrict__ new_xyz,
                int* __restrict__ knn_out)
{
    __shared__ float4 sp[TS];
    const int b = blockIdx.x >> 3;
    const int q = ((blockIdx.x & 7) << 8) + threadIdx.x;

    const float* nb = new_xyz + ((size_t)b * NPOINT + q) * 3;
    const float qx = nb[0], qy = nb[1], qz = nb[2];

    unsigned long long key[KNN];
#pragma unroll
    for (int k = 0; k < KNN; k++)
        key[k] = (0x7F800000ULL << 32) | (unsigned)k;     // +inf, distinct idx
    unsigned long long maxkey = (0x7F800000ULL << 32) | 15u;
    float worstd = __uint_as_float(0x7F800000u);          // +inf

    const float* base = xyz + (size_t)b * NPTS * 3;
    for (int t = 0; t < NPTS; t += TS) {
        __syncthreads();
        for (int p = threadIdx.x; p < TS; p += 256) {
            const float* src = base + (size_t)(t + p) * 3;
            sp[p] = make_float4(src[0], src[1], src[2], 0.0f);
        }
        __syncthreads();
        for (int j = 0; j < TS; j += 4) {
            float4 c0 = sp[j], c1 = sp[j + 1], c2 = sp[j + 2], c3 = sp[j + 3];
            float x0 = qx - c0.x, y0 = qy - c0.y, z0 = qz - c0.z;
            float x1 = qx - c1.x, y1 = qy - c1.y, z1 = qz - c1.z;
            float x2 = qx - c2.x, y2 = qy - c2.y, z2 = qz - c2.z;
            float x3 = qx - c3.x, y3 = qy - c3.y, z3 = qz - c3.z;
            float d0 = x0 * x0; d0 = fmaf(y0, y0, d0); d0 = fmaf(z0, z0, d0);
            float d1 = x1 * x1; d1 = fmaf(y1, y1, d1); d1 = fmaf(z1, z1, d1);
            float d2 = x2 * x2; d2 = fmaf(y2, y2, d2); d2 = fmaf(z2, z2, d2);
            float d3 = x3 * x3; d3 = fmaf(y3, y3, d3); d3 = fmaf(z3, z3, d3);
            float mg = fminf(fminf(d0, d1), fminf(d2, d3));
            if (mg < worstd) {
                float dc[4] = {d0, d1, d2, d3};
#pragma unroll
                for (int c = 0; c < 4; c++) {
                    if (dc[c] < worstd) {
                        unsigned long long nk =
                            ((unsigned long long)__float_as_uint(dc[c]) << 32)
                            | (unsigned)(t + j + c);
#pragma unroll
                        for (int s = 0; s < KNN; s++)
                            if (key[s] == maxkey) key[s] = nk;
                        // depth-4 tree max over 16 keys
                        unsigned long long a0 = umax64(key[0],  key[1]);
                        unsigned long long a1 = umax64(key[2],  key[3]);
                        unsigned long long a2 = umax64(key[4],  key[5]);
                        unsigned long long a3 = umax64(key[6],  key[7]);
                        unsigned long long a4 = umax64(key[8],  key[9]);
                        unsigned long long a5 = umax64(key[10], key[11]);
                        unsigned long long a6 = umax64(key[12], key[13]);
                        unsigned long long a7 = umax64(key[14], key[15]);
                        unsigned long long b0 = umax64(a0, a1);
                        unsigned long long b1 = umax64(a2, a3);
                        unsigned long long b2 = umax64(a4, a5);
                        unsigned long long b3 = umax64(a6, a7);
                        maxkey = umax64(umax64(b0, b1), umax64(b2, b3));
                        worstd = __uint_as_float((unsigned)(maxkey >> 32));
                    }
                }
            }
        }
    }
    int* o = knn_out + ((size_t)b * NPOINT + q) * KNN;
#pragma unroll
    for (int k = 0; k < KNN; k++) o[k] = (int)(unsigned)(key[k] & 0xFFFFFFFFu);
}

// ---------------------------------------------------------------- GEMM -----
__global__ __launch_bounds__(256)
void gemm_kernel(const float* __restrict__ feat,
                 const float* __restrict__ W,
                 const float* __restrict__ bias,
                 float* __restrict__ h)
{
    __shared__ float Wt[CIN * COUT];
    __shared__ float sf[32 * CIN];
    const int tid = threadIdx.x;

    for (int j = tid; j < CIN * COUT; j += 256) {
        int c = j >> 6, k = j & 63;
        Wt[k * COUT + c] = W[j];
    }
    const size_t row0 = (size_t)blockIdx.x * 32;
    const float* fb = feat + row0 * CIN;
    for (int j = tid; j < 32 * CIN; j += 256) sf[j] = fb[j];
    __syncthreads();

    const int cg = tid & 31;
    const int rg = tid >> 5;

    float acc[4][4];
#pragma unroll
    for (int r = 0; r < 4; r++)
#pragma unroll
        for (int c = 0; c < 4; c++) acc[r][c] = 0.0f;

#pragma unroll 8
    for (int k = 0; k < CIN; k++) {
        float4 wv = *(const float4*)&Wt[k * COUT + cg * 4];
        float f0 = sf[(rg * 4 + 0) * CIN + k];
        float f1 = sf[(rg * 4 + 1) * CIN + k];
        float f2 = sf[(rg * 4 + 2) * CIN + k];
        float f3 = sf[(rg * 4 + 3) * CIN + k];
        acc[0][0] = fmaf(f0, wv.x, acc[0][0]);
        acc[0][1] = fmaf(f0, wv.y, acc[0][1]);
        acc[0][2] = fmaf(f0, wv.z, acc[0][2]);
        acc[0][3] = fmaf(f0, wv.w, acc[0][3]);
        acc[1][0] = fmaf(f1, wv.x, acc[1][0]);
        acc[1][1] = fmaf(f1, wv.y, acc[1][1]);
        acc[1][2] = fmaf(f1, wv.z, acc[1][2]);
        acc[1][3] = fmaf(f1, wv.w, acc[1][3]);
        acc[2][0] = fmaf(f2, wv.x, acc[2][0]);
        acc[2][1] = fmaf(f2, wv.y, acc[2][1]);
        acc[2][2] = fmaf(f2, wv.z, acc[2][2]);
        acc[2][3] = fmaf(f2, wv.w, acc[2][3]);
        acc[3][0] = fmaf(f3, wv.x, acc[3][0]);
        acc[3][1] = fmaf(f3, wv.y, acc[3][1]);
        acc[3][2] = fmaf(f3, wv.z, acc[3][2]);
        acc[3][3] = fmaf(f3, wv.w, acc[3][3]);
    }
    const float4 bb = *(const float4*)&bias[cg * 4];
#pragma unroll
    for (int r = 0; r < 4; r++) {
        float4 o;
        o.x = acc[r][0] + bb.x;
        o.y = acc[r][1] + bb.y;
        o.z = acc[r][2] + bb.z;
        o.w = acc[r][3] + bb.w;
        *(float4*)&h[(row0 + rg * 4 + r) * COUT + cg * 4] = o;
    }
}

// ----------------------------------------------------------- BN stats ------
__global__ __launch_bounds__(256)
void stats_kernel(const float* __restrict__ h)
{
    __shared__ float4 reds[8][32];
    __shared__ float4 redq[8][32];
    const int tid = threadIdx.x;
    const int cg  = tid & 31;
    const int r   = tid >> 5;

    const float* p = h + ((size_t)blockIdx.x * 128 + r) * COUT + cg * 4;
    float4 s = make_float4(0.f, 0.f, 0.f, 0.f);
    float4 q = make_float4(0.f, 0.f, 0.f, 0.f);
#pragma unroll
    for (int it = 0; it < 16; it++) {
        float4 v = *(const float4*)(p + (size_t)it * 8 * COUT);
        s.x += v.x; s.y += v.y; s.z += v.z; s.w += v.w;
        q.x = fmaf(v.x, v.x, q.x);
        q.y = fmaf(v.y, v.y, q.y);
        q.z = fmaf(v.z, v.z, q.z);
        q.w = fmaf(v.w, v.w, q.w);
    }
    reds[r][cg] = s;
    redq[r][cg] = q;
    __syncthreads();
    if (r == 0) {
        float4 ts = reds[0][cg], tq = redq[0][cg];
#pragma unroll
        for (int j = 1; j < 8; j++) {
            float4 a = reds[j][cg], b2 = redq[j][cg];
            ts.x += a.x; ts.y += a.y; ts.z += a.z; ts.w += a.w;
            tq.x += b2.x; tq.y += b2.y; tq.z += b2.z; tq.w += b2.w;
        }
        *(float4*)&g_fsum[(size_t)blockIdx.x * COUT + cg * 4] = ts;
        *(float4*)&g_fsq [(size_t)blockIdx.x * COUT + cg * 4] = tq;
    }
}

__global__ __launch_bounds__(128)
void finalize_kernel(const float* __restrict__ gamma, const float* __restrict__ beta)
{
    const int c = threadIdx.x;
    double s0 = 0, s1 = 0, s2 = 0, s3 = 0;
    double q0 = 0, q1 = 0, q2 = 0, q3 = 0;
    for (int blk = 0; blk < 1024; blk += 4) {
        s0 += (double)g_fsum[(blk + 0) * COUT + c];
        s1 += (double)g_fsum[(blk + 1) * COUT + c];
        s2 += (double)g_fsum[(blk + 2) * COUT + c];
        s3 += (double)g_fsum[(blk + 3) * COUT + c];
        q0 += (double)g_fsq [(blk + 0) * COUT + c];
        q1 += (double)g_fsq [(blk + 1) * COUT + c];
        q2 += (double)g_fsq [(blk + 2) * COUT + c];
        q3 += (double)g_fsq [(blk + 3) * COUT + c];
    }
    double s = (s0 + s1) + (s2 + s3);
    double q = (q0 + q1) + (q2 + q3);
    const double inv_n = 1.0 / (double)((size_t)BATCH * NPTS);
    double mean = s * inv_n;
    double var  = q * inv_n - mean * mean;
    double scale = (double)gamma[c] / sqrt(var + 1e-5);
    g_scale[c] = (float)scale;
    g_shift[c] = (float)((double)beta[c] - mean * scale);
}

// -------------------------------------------------- gather + maxpool -------
__global__ __launch_bounds__(128)
void maxpool_kernel(const float* __restrict__ h,
                    const int* __restrict__ knn,
                    float* __restrict__ out_feat)
{
    __shared__ int sidx[KNN];
    const int b = blockIdx.x >> 11;
    const int q = blockIdx.x & 2047;
    const int c = threadIdx.x;
    if (c < KNN) sidx[c] = knn[((size_t)b * NPOINT + q) * KNN + c];
    __syncthreads();

    const float sc = g_scale[c], sh = g_shift[c];
    const float* hb = h + (size_t)b * NPTS * COUT;
    float m = -3.4e38f;
#pragma unroll
    for (int k = 0; k < KNN; k++) {
        float v = hb[(size_t)sidx[k] * COUT + c];
        m = fmaxf(m, fmaf(v, sc, sh));
    }
    m = fmaxf(m, 0.0f);
    out_feat[((size_t)b * NPOINT + q) * COUT + c] = m;
}

// ---------------------------------------------------------------------------
extern "C" void kernel_launch(void* const* d_in, const int* in_sizes, int n_in,
                              void* d_out, int out_size)
{
    const float* xyz   = (const float*)d_in[0];
    const float* feat  = (const float*)d_in[1];
    const float* W     = (const float*)d_in[2];
    const float* bias  = (const float*)d_in[3];
    const float* gamma = (const float*)d_in[4];
    const float* beta  = (const float*)d_in[5];

    float* out      = (float*)d_out;
    float* out_xyz  = out;
    float* out_feat = out + ((size_t)out_size - (size_t)BATCH * NPOINT * COUT);

    cudaFuncSetAttribute(fps_kernel, cudaFuncAttributeMaxDynamicSharedMemorySize,
                         FPS_SMEM_BYTES);

    // knn placed 4th: ncu empirically captures the 4th launch -> profile knn.
    fps_kernel<<<BATCH, FPT, FPS_SMEM_BYTES>>>(xyz, out_xyz);
    gemm_kernel<<<(BATCH * NPTS) / 32, 256>>>(feat, W, bias, g_h);
    stats_kernel<<<1024, 256>>>(g_h);
    knn_kernel<<<BATCH * 8, 256>>>(xyz, out_xyz, g_knn);
    finalize_kernel<<<1, 128>>>(gamma, beta);
    maxpool_kernel<<<BATCH * NPOINT, 128>>>(g_h, g_knn, out_feat);
    (void)n_in; (void)in_sizes;
}